// round 14
// baseline (speedup 1.0000x reference)
#include <cuda_runtime.h>
#include <cuda_bf16.h>
#include <math.h>
#include <cstdint>

#define POI   5000
#define EMB   256
#define UNITS 512
#define QDIM  256
#define BATCH 64
#define X1DIM  (EMB + QDIM)        // 512
#define NCH    10                  // context p-chunks (5000/10 = 500)

// ---------------- scratch (no cudaMalloc allowed; disjoint per concurrent use) --
__device__ float g_h[BATCH * UNITS];
__device__ float g_qproj[BATCH * UNITS];
__device__ float g_ctx[BATCH * EMB];
__device__ float g_vproj[POI * UNITS];                 // 10.24 MB
__device__ float g_score[BATCH * POI];                 // holds exp(score)
__device__ float g_ctxpart[NCH * BATCH * EMB];
__device__ float g_ctxsums[NCH * BATCH];
__device__ float g_gru_part[16 * BATCH * 3 * UNITS];   // 6.3 MB
__device__ float g_qp_part[8 * BATCH * UNITS];         // 1.0 MB
__device__ float g_fc_part[10 * BATCH * POI];          // 12.8 MB
__device__ __nv_bfloat16 g_emb_bf[POI * EMB];          // 2.56 MB
__device__ __nv_bfloat16 g_w1t_bf[UNITS * EMB];        // 0.26 MB (W1 transposed)

// ---------------- fp32 -> bf16 conversion (emb row-major, W1 transposed) --------
__global__ void convert_bf16_kernel(const float* __restrict__ emb,
                                    const float* __restrict__ W1,
                                    __nv_bfloat16* __restrict__ emb_bf,
                                    __nv_bfloat16* __restrict__ w1t_bf) {
    int idx = blockIdx.x * 256 + threadIdx.x;
    if (idx < POI * EMB) emb_bf[idx] = __float2bfloat16(emb[idx]);
    if (idx < UNITS * EMB) {
        int u = idx >> 8;          // /EMB
        int k = idx & 255;
        w1t_bf[idx] = __float2bfloat16(W1[k * UNITS + u]);
    }
}

// ---------------- vproj via HMMA (mma.sync m16n8k16 bf16) — R12-proven ----------
__global__ void __launch_bounds__(256)
vproj_hmma_kernel(const __nv_bfloat16* __restrict__ emb_bf,
                  const __nv_bfloat16* __restrict__ w1t_bf,
                  const float* __restrict__ W1_b,
                  float* __restrict__ vproj) {
    const int warp = threadIdx.x >> 5;
    const int lane = threadIdx.x & 31;
    const int grp = lane >> 2;
    const int qid = lane & 3;
    const int n0 = blockIdx.x * 64;
    const int m0 = blockIdx.y * 128 + warp * 16;

    const int row0 = m0 + grp;
    const int row1 = m0 + grp + 8;
    const bool v0 = row0 < POI;
    const bool v1 = row1 < POI;

    float d[8][4];
#pragma unroll
    for (int nt = 0; nt < 8; nt++)
#pragma unroll
        for (int j = 0; j < 4; j++) d[nt][j] = 0.f;

#pragma unroll 4
    for (int k0 = 0; k0 < EMB; k0 += 16) {
        uint32_t a0 = 0, a1 = 0, a2 = 0, a3 = 0;
        if (v0) {
            const uint32_t* pa = (const uint32_t*)(emb_bf + (size_t)row0 * EMB + k0 + qid * 2);
            a0 = pa[0];
            a2 = pa[4];
        }
        if (v1) {
            const uint32_t* pa = (const uint32_t*)(emb_bf + (size_t)row1 * EMB + k0 + qid * 2);
            a1 = pa[0];
            a3 = pa[4];
        }
#pragma unroll
        for (int nt = 0; nt < 8; nt++) {
            const uint32_t* pb = (const uint32_t*)(w1t_bf + (size_t)(n0 + nt * 8 + grp) * EMB + k0 + qid * 2);
            uint32_t b0 = pb[0];
            uint32_t b1 = pb[4];
            asm volatile(
                "mma.sync.aligned.m16n8k16.row.col.f32.bf16.bf16.f32 "
                "{%0,%1,%2,%3}, {%4,%5,%6,%7}, {%8,%9}, {%0,%1,%2,%3};"
                : "+f"(d[nt][0]), "+f"(d[nt][1]), "+f"(d[nt][2]), "+f"(d[nt][3])
                : "r"(a0), "r"(a1), "r"(a2), "r"(a3), "r"(b0), "r"(b1));
        }
    }

    if (v0) {
        float* dst = vproj + (size_t)row0 * UNITS;
#pragma unroll
        for (int nt = 0; nt < 8; nt++) {
            int n = n0 + nt * 8 + qid * 2;
            float2 v = make_float2(d[nt][0] + W1_b[n], d[nt][1] + W1_b[n + 1]);
            *(float2*)(dst + n) = v;
        }
    }
    if (v1) {
        float* dst = vproj + (size_t)row1 * UNITS;
#pragma unroll
        for (int nt = 0; nt < 8; nt++) {
            int n = n0 + nt * 8 + qid * 2;
            float2 v = make_float2(d[nt][2] + W1_b[n], d[nt][3] + W1_b[n + 1]);
            *(float2*)(dst + n) = v;
        }
    }
}

// ---------------- gemm_v2: C[M,N] = A[M,K] @ W[K,N] (+bias iff gridDim.z==1) -----
template <int BM, int BN, int TM, int TN>
__global__ void gemm_v2_kernel(const float* __restrict__ A,
                               const float* __restrict__ W,
                               const float* __restrict__ bias,
                               float* __restrict__ out,
                               int M, int N, int K, int kchunk) {
    __shared__ float As[32][BM + 1];
    __shared__ float Ws[32][BN];
    const int tid = threadIdx.x;
    const int r = tid >> 4;
    const int c = tid & 15;
    const int n0 = blockIdx.x * BN;
    const int m0 = blockIdx.y * BM;
    const int kbase = blockIdx.z * kchunk;

    float acc[TM][TN];
#pragma unroll
    for (int i = 0; i < TM; i++)
#pragma unroll
        for (int j = 0; j < TN; j++) acc[i][j] = 0.f;

    for (int kk = kbase; kk < kbase + kchunk; kk += 32) {
#pragma unroll
        for (int pass = 0; pass < (BM * 32) / 1024; pass++) {
            int idx = pass * 1024 + tid * 4;
            int m = idx >> 5;
            int k = idx & 31;
            float4 v = make_float4(0.f, 0.f, 0.f, 0.f);
            if (m0 + m < M) v = *(const float4*)(A + (size_t)(m0 + m) * K + kk + k);
            As[k + 0][m] = v.x;
            As[k + 1][m] = v.y;
            As[k + 2][m] = v.z;
            As[k + 3][m] = v.w;
        }
#pragma unroll
        for (int pass = 0; pass < (32 * BN) / 1024; pass++) {
            int idx = pass * 1024 + tid * 4;
            int k = idx / BN;
            int n = idx % BN;
            float4 v = make_float4(0.f, 0.f, 0.f, 0.f);
            if (n0 + n < N) v = *(const float4*)(W + (size_t)(kk + k) * N + n0 + n);
            *(float4*)&Ws[k][n] = v;
        }
        __syncthreads();
#pragma unroll
        for (int k = 0; k < 32; k++) {
            float a[TM];
#pragma unroll
            for (int i = 0; i < TM; i++) a[i] = As[k][r * TM + i];
            float b[TN];
#pragma unroll
            for (int j = 0; j < TN; j += 4)
                *(float4*)&b[j] = *(const float4*)&Ws[k][c * TN + j];
#pragma unroll
            for (int i = 0; i < TM; i++)
#pragma unroll
                for (int j = 0; j < TN; j++)
                    acc[i][j] = fmaf(a[i], b[j], acc[i][j]);
        }
        __syncthreads();
    }

    const bool direct = (gridDim.z == 1);
    float* dst = direct ? out : out + (size_t)blockIdx.z * M * N;
#pragma unroll
    for (int i = 0; i < TM; i++) {
        int m = m0 + r * TM + i;
        if (m >= M) continue;
#pragma unroll
        for (int j = 0; j < TN; j += 4) {
            int n = n0 + c * TN + j;
            if (n < N) {
                float4 v;
                v.x = acc[i][j + 0] + (direct ? bias[n + 0] : 0.f);
                v.y = acc[i][j + 1] + (direct ? bias[n + 1] : 0.f);
                v.z = acc[i][j + 2] + (direct ? bias[n + 2] : 0.f);
                v.w = acc[i][j + 3] + (direct ? bias[n + 3] : 0.f);
                *(float4*)(dst + (size_t)m * N + n) = v;
            }
        }
    }
}

// ---------------- merged GRU matmuls: slabs 0..7 = xm (x1 built inline), 8..15 = hm
__global__ void gru_mm_kernel(const int* __restrict__ x,
                              const float* __restrict__ query,
                              const float* __restrict__ emb,
                              const float* __restrict__ dec_hidden,
                              const float* __restrict__ Wk,
                              const float* __restrict__ Wr,
                              float* __restrict__ part) {
    const int NN = 3 * UNITS;
    __shared__ float As[32][65];
    __shared__ float Ws[32][64];
    const int tid = threadIdx.x;
    const int r = tid >> 4;
    const int c = tid & 15;
    const int n0 = blockIdx.x * 64;
    const bool isX = blockIdx.z < 8;
    const int kbase = (isX ? blockIdx.z : blockIdx.z - 8) * 64;
    const float* W = isX ? Wk : Wr;

    float acc[4][4];
#pragma unroll
    for (int i = 0; i < 4; i++)
#pragma unroll
        for (int j = 0; j < 4; j++) acc[i][j] = 0.f;

    for (int kk = kbase; kk < kbase + 64; kk += 32) {
#pragma unroll
        for (int pass = 0; pass < 2; pass++) {
            int idx = pass * 1024 + tid * 4;
            int m = idx >> 5;
            int k = idx & 31;
            int gk = kk + k;
            float4 v;
            if (isX) {
                if (gk < EMB)
                    v = *(const float4*)(emb + (size_t)x[m] * EMB + gk);
                else
                    v = *(const float4*)(query + (size_t)m * QDIM + gk - EMB);
            } else {
                v = *(const float4*)(dec_hidden + (size_t)m * UNITS + gk);
            }
            As[k + 0][m] = v.x;
            As[k + 1][m] = v.y;
            As[k + 2][m] = v.z;
            As[k + 3][m] = v.w;
        }
#pragma unroll
        for (int pass = 0; pass < 2; pass++) {
            int idx = pass * 1024 + tid * 4;
            int k = idx >> 6;
            int n = idx & 63;
            *(float4*)&Ws[k][n] = *(const float4*)(W + (size_t)(kk + k) * NN + n0 + n);
        }
        __syncthreads();
#pragma unroll
        for (int k = 0; k < 32; k++) {
            float a0 = As[k][r * 4 + 0];
            float a1 = As[k][r * 4 + 1];
            float a2 = As[k][r * 4 + 2];
            float a3 = As[k][r * 4 + 3];
            float4 b = *(const float4*)&Ws[k][c * 4];
            acc[0][0] = fmaf(a0, b.x, acc[0][0]); acc[0][1] = fmaf(a0, b.y, acc[0][1]);
            acc[0][2] = fmaf(a0, b.z, acc[0][2]); acc[0][3] = fmaf(a0, b.w, acc[0][3]);
            acc[1][0] = fmaf(a1, b.x, acc[1][0]); acc[1][1] = fmaf(a1, b.y, acc[1][1]);
            acc[1][2] = fmaf(a1, b.z, acc[1][2]); acc[1][3] = fmaf(a1, b.w, acc[1][3]);
            acc[2][0] = fmaf(a2, b.x, acc[2][0]); acc[2][1] = fmaf(a2, b.y, acc[2][1]);
            acc[2][2] = fmaf(a2, b.z, acc[2][2]); acc[2][3] = fmaf(a2, b.w, acc[2][3]);
            acc[3][0] = fmaf(a3, b.x, acc[3][0]); acc[3][1] = fmaf(a3, b.y, acc[3][1]);
            acc[3][2] = fmaf(a3, b.z, acc[3][2]); acc[3][3] = fmaf(a3, b.w, acc[3][3]);
        }
        __syncthreads();
    }

    float* dst = part + (size_t)blockIdx.z * BATCH * NN;
#pragma unroll
    for (int i = 0; i < 4; i++) {
        int m = r * 4 + i;
        int n = n0 + c * 4;
        float4 v = make_float4(acc[i][0], acc[i][1], acc[i][2], acc[i][3]);
        *(float4*)(dst + (size_t)m * NN + n) = v;
    }
}

// ---------------- reduce K-split partials + bias ----------------
__global__ void reduce_bias_kernel(const float* __restrict__ part,
                                   const float* __restrict__ bias,
                                   float* __restrict__ C,
                                   int MN, int N, int S) {
    int i = blockIdx.x * 256 + threadIdx.x;
    if (i >= MN) return;
    float s = 0.f;
    for (int z = 0; z < S; z++) s += part[(size_t)z * MN + i];
    C[i] = s + bias[i % N];
}

// ---------------- GRU gates: sums 8 xm slabs + 8 hm slabs + bias ----------------
__global__ void gru_gates_kernel(const float* __restrict__ part,
                                 const float* __restrict__ bias,
                                 const float* __restrict__ h_in,
                                 float* __restrict__ h_scratch,
                                 float* __restrict__ out_state,
                                 float* __restrict__ out_output) {
    const int NN = 3 * UNITS;
    int b = blockIdx.x;
    int u = threadIdx.x;               // 512
    float xz = bias[u], xr = bias[UNITS + u], xh = bias[2 * UNITS + u];
    float hz = bias[NN + u], hr = bias[NN + UNITS + u], hh = bias[NN + 2 * UNITS + u];
#pragma unroll
    for (int z = 0; z < 8; z++) {
        const float* px = part + (size_t)z * BATCH * NN + b * NN;
        const float* ph = part + (size_t)(8 + z) * BATCH * NN + b * NN;
        xz += px[u]; xr += px[UNITS + u]; xh += px[2 * UNITS + u];
        hz += ph[u]; hr += ph[UNITS + u]; hh += ph[2 * UNITS + u];
    }
    float z = 1.f / (1.f + expf(-(xz + hz)));
    float r = 1.f / (1.f + expf(-(xr + hr)));
    float hc = tanhf(xh + r * hh);
    float h = h_in[b * UNITS + u];
    float hn = z * h + (1.f - z) * hc;
    h_scratch[b * UNITS + u] = hn;
    if (out_state)  out_state[b * UNITS + u] = hn;
    if (out_output) out_output[b * UNITS + u] = hn;
}

// ---------------- attention: f16x2 tanh (2 MUFU lanes/op), writes exp(score) ----
// grid (ceil(POI/128), BATCH/4), block 128. tanh in [-1,1] bounds |score| ~ 20,
// so unshifted exp is safe in fp32.
__global__ void attn_score_kernel(const float* __restrict__ vproj,
                                  const float* __restrict__ qproj,
                                  const float* __restrict__ Vw,
                                  const float* __restrict__ Vb,
                                  float* __restrict__ score_exp) {
    __shared__ float q_s[4][UNITS];    // 8 KB
    __shared__ uint32_t vw2_s[UNITS / 2];  // f16x2-packed Vw, 1 KB
    __shared__ float v_s[128][33];     // 16.9 KB
    const int tid = threadIdx.x;       // 128
    const int p0 = blockIdx.x * 128;
    const int b0 = blockIdx.y * 4;

    for (int t = tid; t < 4 * UNITS; t += 128) {
        int b = t >> 9, u = t & 511;
        q_s[b][u] = qproj[(b0 + b) * UNITS + u];
    }
    for (int t = tid; t < UNITS / 2; t += 128) {
        float lo = Vw[2 * t], hi = Vw[2 * t + 1];
        uint32_t packed;
        asm("cvt.rn.f16x2.f32 %0, %1, %2;" : "=r"(packed) : "f"(hi), "f"(lo));
        vw2_s[t] = packed;
    }

    uint32_t acc2[4] = {0u, 0u, 0u, 0u};   // f16x2 accumulators (start at {0,0})
    for (int u0 = 0; u0 < UNITS; u0 += 32) {
        __syncthreads();                    // also covers q_s/vw2_s on first iter
        for (int t = tid; t < 128 * 32; t += 128) {
            int p = t >> 5, j = t & 31;
            v_s[p][j] = (p0 + p < POI) ? vproj[(size_t)(p0 + p) * UNITS + u0 + j] : 0.f;
        }
        __syncthreads();
#pragma unroll
        for (int j = 0; j < 32; j += 2) {
            float va = v_s[tid][j];
            float vb = v_s[tid][j + 1];
            uint32_t vw2 = vw2_s[(u0 + j) >> 1];
#pragma unroll
            for (int b = 0; b < 4; b++) {
                float s0 = va + q_s[b][u0 + j];
                float s1 = vb + q_s[b][u0 + j + 1];
                uint32_t s2, t2;
                asm("cvt.rn.f16x2.f32 %0, %1, %2;" : "=r"(s2) : "f"(s1), "f"(s0));
                asm("tanh.approx.f16x2 %0, %1;" : "=r"(t2) : "r"(s2));
                asm("fma.rn.f16x2 %0, %1, %2, %0;" : "+r"(acc2[b]) : "r"(vw2), "r"(t2));
            }
        }
    }
    if (p0 + tid < POI) {
        float vbias = Vb[0];
#pragma unroll
        for (int b = 0; b < 4; b++) {
            __half2 h2 = *(__half2*)&acc2[b];
            float2 f2 = __half22float2(h2);
            score_exp[(size_t)(b0 + b) * POI + p0 + tid] = __expf(f2.x + f2.y + vbias);
        }
    }
}

// ---------------- context partials over exp weights + per-chunk exp-sums --------
__global__ void context_partial_kernel(const float* __restrict__ eattn,
                                       const float* __restrict__ emb,
                                       float* __restrict__ part,
                                       float* __restrict__ sums) {
    const int PC = POI / NCH;          // 500
    int b0 = blockIdx.x * 4;
    int ch = blockIdx.y;
    int e  = threadIdx.x;              // 256 == EMB
    int p0 = ch * PC;
    const float* a0 = eattn + (size_t)(b0 + 0) * POI;
    const float* a1 = eattn + (size_t)(b0 + 1) * POI;
    const float* a2 = eattn + (size_t)(b0 + 2) * POI;
    const float* a3 = eattn + (size_t)(b0 + 3) * POI;
    float c0 = 0.f, c1 = 0.f, c2 = 0.f, c3 = 0.f;
    float s0 = 0.f, s1 = 0.f, s2 = 0.f, s3 = 0.f;
#pragma unroll 4
    for (int p = p0; p < p0 + PC; ++p) {
        float w0 = a0[p], w1 = a1[p], w2 = a2[p], w3 = a3[p];
        float ev = emb[p * EMB + e];
        c0 = fmaf(w0, ev, c0); s0 += w0;
        c1 = fmaf(w1, ev, c1); s1 += w1;
        c2 = fmaf(w2, ev, c2); s2 += w2;
        c3 = fmaf(w3, ev, c3); s3 += w3;
    }
    part[(ch * BATCH + b0 + 0) * EMB + e] = c0;
    part[(ch * BATCH + b0 + 1) * EMB + e] = c1;
    part[(ch * BATCH + b0 + 2) * EMB + e] = c2;
    part[(ch * BATCH + b0 + 3) * EMB + e] = c3;
    if (e == 0) {
        sums[ch * BATCH + b0 + 0] = s0;
        sums[ch * BATCH + b0 + 1] = s1;
        sums[ch * BATCH + b0 + 2] = s2;
        sums[ch * BATCH + b0 + 3] = s3;
    }
}

// ---------------- ctx = (sum of partials) / (sum of exp) ----------------
__global__ void ctx_reduce_kernel(const float* __restrict__ part,
                                  const float* __restrict__ sums,
                                  float* __restrict__ ctx) {
    int b = blockIdx.x;
    int e = threadIdx.x;               // 256
    float num = 0.f, den = 0.f;
#pragma unroll
    for (int ch = 0; ch < NCH; ch++) {
        num += part[(ch * BATCH + b) * EMB + e];
        den += sums[ch * BATCH + b];
    }
    ctx[b * EMB + e] = num / den;
}

// ---------------- launch ----------------
extern "C" void kernel_launch(void* const* d_in, const int* in_sizes, int n_in,
                              void* d_out, int out_size) {
    const int*   x          = (const int*)  d_in[0];
    const float* query      = (const float*)d_in[1];
    const float* emb        = (const float*)d_in[2];
    // d_in[3] = A_hat (unused)
    const float* dec_hidden = (const float*)d_in[4];
    const float* cat_dec    = (const float*)d_in[5];
    const float* gru_kernel = (const float*)d_in[6];
    const float* gru_rec    = (const float*)d_in[7];
    const float* gru_bias   = (const float*)d_in[8];
    const float* W1_w       = (const float*)d_in[9];
    const float* W1_b       = (const float*)d_in[10];
    const float* W2_w       = (const float*)d_in[11];
    const float* W2_b       = (const float*)d_in[12];
    const float* V_w        = (const float*)d_in[13];
    const float* V_b        = (const float*)d_in[14];
    const float* fc_w       = (const float*)d_in[15];
    const float* fc_b       = (const float*)d_in[16];

    float* out        = (float*)d_out;
    float* out_logits = out;
    float* out_state  = (out_size >= BATCH * POI + BATCH * UNITS)
                        ? out + BATCH * POI : nullptr;
    float* out_output = (out_size >= BATCH * POI + 2 * BATCH * UNITS)
                        ? out + BATCH * POI + BATCH * UNITS : nullptr;

    float *g_h_p, *g_qp_p, *g_ctx_p, *g_vp_p, *g_sc_p, *g_cp_p, *g_cs_p;
    float *g_grup_p, *g_qpp_p, *g_fcp_p;
    __nv_bfloat16 *g_embbf_p, *g_w1tbf_p;
    cudaGetSymbolAddress((void**)&g_h_p,     g_h);
    cudaGetSymbolAddress((void**)&g_qp_p,    g_qproj);
    cudaGetSymbolAddress((void**)&g_ctx_p,   g_ctx);
    cudaGetSymbolAddress((void**)&g_vp_p,    g_vproj);
    cudaGetSymbolAddress((void**)&g_sc_p,    g_score);
    cudaGetSymbolAddress((void**)&g_cp_p,    g_ctxpart);
    cudaGetSymbolAddress((void**)&g_cs_p,    g_ctxsums);
    cudaGetSymbolAddress((void**)&g_grup_p,  g_gru_part);
    cudaGetSymbolAddress((void**)&g_qpp_p,   g_qp_part);
    cudaGetSymbolAddress((void**)&g_fcp_p,   g_fc_part);
    cudaGetSymbolAddress((void**)&g_embbf_p, g_emb_bf);
    cudaGetSymbolAddress((void**)&g_w1tbf_p, g_w1t_bf);

    // One-time stream/event setup (on the uncaptured correctness call).
    static cudaStream_t s2 = nullptr, s3 = nullptr;
    static cudaEvent_t evFork = nullptr, evVP = nullptr, evH = nullptr, evFC = nullptr;
    if (!s2) {
        cudaStreamCreateWithFlags(&s2, cudaStreamNonBlocking);
        cudaStreamCreateWithFlags(&s3, cudaStreamNonBlocking);
        cudaEventCreateWithFlags(&evFork, cudaEventDisableTiming);
        cudaEventCreateWithFlags(&evVP, cudaEventDisableTiming);
        cudaEventCreateWithFlags(&evH, cudaEventDisableTiming);
        cudaEventCreateWithFlags(&evFC, cudaEventDisableTiming);
    }

    // ---- fork ----
    cudaEventRecord(evFork, 0);
    cudaStreamWaitEvent(s2, evFork, 0);
    cudaStreamWaitEvent(s3, evFork, 0);

    // s2: bf16 convert, then vproj via HMMA tensor cores (320 CTAs)
    convert_bf16_kernel<<<(POI * EMB + 255) / 256, 256, 0, s2>>>(
        emb, W1_w, g_embbf_p, g_w1tbf_p);
    vproj_hmma_kernel<<<dim3(UNITS / 64, (POI + 127) / 128), 256, 0, s2>>>(
        g_embbf_p, g_w1tbf_p, W1_b, g_vp_p);
    cudaEventRecord(evVP, s2);

    // s3: fc cat_dec term (K rows 768..1279), slabs 0..3 — needs only inputs
    gemm_v2_kernel<64, 128, 4, 8><<<dim3((POI + 127) / 128, 1, 4), 256, 0, s3>>>(
        cat_dec, fc_w + (size_t)(EMB + UNITS) * POI, nullptr, g_fcp_p,
        BATCH, POI, UNITS, 128);

    // main: GRU chain
    gru_mm_kernel<<<dim3(3 * UNITS / 64, 1, 16), 256>>>(
        x, query, emb, dec_hidden, gru_kernel, gru_rec, g_grup_p);
    gru_gates_kernel<<<BATCH, UNITS>>>(g_grup_p, gru_bias, dec_hidden,
                                       g_h_p, out_state, out_output);
    cudaEventRecord(evH, 0);

    // s3: fc output_ term (K rows 256..767), slabs 4..7 — needs h
    cudaStreamWaitEvent(s3, evH, 0);
    gemm_v2_kernel<64, 128, 4, 8><<<dim3((POI + 127) / 128, 1, 4), 256, 0, s3>>>(
        g_h_p, fc_w + (size_t)EMB * POI, nullptr, g_fcp_p + (size_t)4 * BATCH * POI,
        BATCH, POI, UNITS, 128);
    cudaEventRecord(evFC, s3);

    // main: q_proj = h @ W2 + b (split 8, then reduce — cheap, avoids 37MB re-read)
    gemm_v2_kernel<64, 64, 4, 4><<<dim3(UNITS / 64, 1, 8), 256>>>(
        g_h_p, W2_w, nullptr, g_qpp_p, BATCH, UNITS, UNITS, 64);
    reduce_bias_kernel<<<(BATCH * UNITS + 255) / 256, 256>>>(
        g_qpp_p, W2_b, g_qp_p, BATCH * UNITS, UNITS, 8);

    // main: attention (waits on vproj); f16x2 tanh, writes exp(score)
    cudaStreamWaitEvent(0, evVP, 0);
    attn_score_kernel<<<dim3((POI + 127) / 128, BATCH / 4), 128>>>(
        g_vp_p, g_qp_p, V_w, V_b, g_sc_p);

    // main: context partials (exp-weighted) + per-chunk exp sums, then normalize
    context_partial_kernel<<<dim3(BATCH / 4, NCH), 256>>>(g_sc_p, emb, g_cp_p, g_cs_p);
    ctx_reduce_kernel<<<BATCH, 256>>>(g_cp_p, g_cs_p, g_ctx_p);

    // main: fc context term (K rows 0..255), slabs 8..9
    gemm_v2_kernel<64, 128, 4, 8><<<dim3((POI + 127) / 128, 1, 2), 256>>>(
        g_ctx_p, fc_w, nullptr, g_fcp_p + (size_t)8 * BATCH * POI,
        BATCH, POI, EMB, 128);

    // main: final reduce over 10 slabs + bias (waits on s3's fc terms)
    cudaStreamWaitEvent(0, evFC, 0);
    reduce_bias_kernel<<<(BATCH * POI + 255) / 256, 256>>>(
        g_fcp_p, fc_b, out_logits, BATCH * POI, POI, 10);
}

// round 15
// speedup vs baseline: 1.1108x; 1.1108x over previous
#include <cuda_runtime.h>
#include <cuda_bf16.h>
#include <math.h>
#include <cstdint>

#define POI   5000
#define EMB   256
#define UNITS 512
#define QDIM  256
#define BATCH 64
#define X1DIM  (EMB + QDIM)        // 512
#define NCH    10                  // context p-chunks (5000/10 = 500)

// ---------------- scratch (no cudaMalloc allowed; disjoint per concurrent use) --
__device__ float g_h[BATCH * UNITS];
__device__ float g_qproj[BATCH * UNITS];
__device__ float g_ctx[BATCH * EMB];
__device__ float g_vproj[POI * UNITS];                 // 10.24 MB
__device__ float g_score[BATCH * POI];                 // holds exp(score)
__device__ float g_ctxpart[NCH * BATCH * EMB];
__device__ float g_ctxsums[NCH * BATCH];
__device__ float g_gru_part[16 * BATCH * 3 * UNITS];   // 6.3 MB
__device__ float g_qp_part[8 * BATCH * UNITS];         // 1.0 MB
__device__ float g_fc_part[10 * BATCH * POI];          // 12.8 MB
__device__ __nv_bfloat16 g_emb_bf[POI * EMB];          // 2.56 MB
__device__ __nv_bfloat16 g_w1t_bf[UNITS * EMB];        // 0.26 MB (W1 transposed)

__device__ __forceinline__ float tanh_ap(float x) {
    float y;
    asm("tanh.approx.f32 %0, %1;" : "=f"(y) : "f"(x));
    return y;
}

// ---------------- fp32 -> bf16 conversion (emb row-major, W1 transposed) --------
__global__ void convert_bf16_kernel(const float* __restrict__ emb,
                                    const float* __restrict__ W1,
                                    __nv_bfloat16* __restrict__ emb_bf,
                                    __nv_bfloat16* __restrict__ w1t_bf) {
    int idx = blockIdx.x * 256 + threadIdx.x;
    if (idx < POI * EMB) emb_bf[idx] = __float2bfloat16(emb[idx]);
    if (idx < UNITS * EMB) {
        int u = idx >> 8;          // /EMB
        int k = idx & 255;
        w1t_bf[idx] = __float2bfloat16(W1[k * UNITS + u]);
    }
}

// ---------------- vproj via HMMA (mma.sync m16n8k16 bf16) — R12-proven ----------
__global__ void __launch_bounds__(256)
vproj_hmma_kernel(const __nv_bfloat16* __restrict__ emb_bf,
                  const __nv_bfloat16* __restrict__ w1t_bf,
                  const float* __restrict__ W1_b,
                  float* __restrict__ vproj) {
    const int warp = threadIdx.x >> 5;
    const int lane = threadIdx.x & 31;
    const int grp = lane >> 2;
    const int qid = lane & 3;
    const int n0 = blockIdx.x * 64;
    const int m0 = blockIdx.y * 128 + warp * 16;

    const int row0 = m0 + grp;
    const int row1 = m0 + grp + 8;
    const bool v0 = row0 < POI;
    const bool v1 = row1 < POI;

    float d[8][4];
#pragma unroll
    for (int nt = 0; nt < 8; nt++)
#pragma unroll
        for (int j = 0; j < 4; j++) d[nt][j] = 0.f;

#pragma unroll 4
    for (int k0 = 0; k0 < EMB; k0 += 16) {
        uint32_t a0 = 0, a1 = 0, a2 = 0, a3 = 0;
        if (v0) {
            const uint32_t* pa = (const uint32_t*)(emb_bf + (size_t)row0 * EMB + k0 + qid * 2);
            a0 = pa[0];
            a2 = pa[4];
        }
        if (v1) {
            const uint32_t* pa = (const uint32_t*)(emb_bf + (size_t)row1 * EMB + k0 + qid * 2);
            a1 = pa[0];
            a3 = pa[4];
        }
#pragma unroll
        for (int nt = 0; nt < 8; nt++) {
            const uint32_t* pb = (const uint32_t*)(w1t_bf + (size_t)(n0 + nt * 8 + grp) * EMB + k0 + qid * 2);
            uint32_t b0 = pb[0];
            uint32_t b1 = pb[4];
            asm volatile(
                "mma.sync.aligned.m16n8k16.row.col.f32.bf16.bf16.f32 "
                "{%0,%1,%2,%3}, {%4,%5,%6,%7}, {%8,%9}, {%0,%1,%2,%3};"
                : "+f"(d[nt][0]), "+f"(d[nt][1]), "+f"(d[nt][2]), "+f"(d[nt][3])
                : "r"(a0), "r"(a1), "r"(a2), "r"(a3), "r"(b0), "r"(b1));
        }
    }

    if (v0) {
        float* dst = vproj + (size_t)row0 * UNITS;
#pragma unroll
        for (int nt = 0; nt < 8; nt++) {
            int n = n0 + nt * 8 + qid * 2;
            float2 v = make_float2(d[nt][0] + W1_b[n], d[nt][1] + W1_b[n + 1]);
            *(float2*)(dst + n) = v;
        }
    }
    if (v1) {
        float* dst = vproj + (size_t)row1 * UNITS;
#pragma unroll
        for (int nt = 0; nt < 8; nt++) {
            int n = n0 + nt * 8 + qid * 2;
            float2 v = make_float2(d[nt][2] + W1_b[n], d[nt][3] + W1_b[n + 1]);
            *(float2*)(dst + n) = v;
        }
    }
}

// ---------------- gemm_v2: C[M,N] = A[M,K] @ W[K,N] (+bias iff gridDim.z==1) -----
template <int BM, int BN, int TM, int TN>
__global__ void gemm_v2_kernel(const float* __restrict__ A,
                               const float* __restrict__ W,
                               const float* __restrict__ bias,
                               float* __restrict__ out,
                               int M, int N, int K, int kchunk) {
    __shared__ float As[32][BM + 1];
    __shared__ float Ws[32][BN];
    const int tid = threadIdx.x;
    const int r = tid >> 4;
    const int c = tid & 15;
    const int n0 = blockIdx.x * BN;
    const int m0 = blockIdx.y * BM;
    const int kbase = blockIdx.z * kchunk;

    float acc[TM][TN];
#pragma unroll
    for (int i = 0; i < TM; i++)
#pragma unroll
        for (int j = 0; j < TN; j++) acc[i][j] = 0.f;

    for (int kk = kbase; kk < kbase + kchunk; kk += 32) {
#pragma unroll
        for (int pass = 0; pass < (BM * 32) / 1024; pass++) {
            int idx = pass * 1024 + tid * 4;
            int m = idx >> 5;
            int k = idx & 31;
            float4 v = make_float4(0.f, 0.f, 0.f, 0.f);
            if (m0 + m < M) v = *(const float4*)(A + (size_t)(m0 + m) * K + kk + k);
            As[k + 0][m] = v.x;
            As[k + 1][m] = v.y;
            As[k + 2][m] = v.z;
            As[k + 3][m] = v.w;
        }
#pragma unroll
        for (int pass = 0; pass < (32 * BN) / 1024; pass++) {
            int idx = pass * 1024 + tid * 4;
            int k = idx / BN;
            int n = idx % BN;
            float4 v = make_float4(0.f, 0.f, 0.f, 0.f);
            if (n0 + n < N) v = *(const float4*)(W + (size_t)(kk + k) * N + n0 + n);
            *(float4*)&Ws[k][n] = v;
        }
        __syncthreads();
#pragma unroll
        for (int k = 0; k < 32; k++) {
            float a[TM];
#pragma unroll
            for (int i = 0; i < TM; i++) a[i] = As[k][r * TM + i];
            float b[TN];
#pragma unroll
            for (int j = 0; j < TN; j += 4)
                *(float4*)&b[j] = *(const float4*)&Ws[k][c * TN + j];
#pragma unroll
            for (int i = 0; i < TM; i++)
#pragma unroll
                for (int j = 0; j < TN; j++)
                    acc[i][j] = fmaf(a[i], b[j], acc[i][j]);
        }
        __syncthreads();
    }

    const bool direct = (gridDim.z == 1);
    float* dst = direct ? out : out + (size_t)blockIdx.z * M * N;
#pragma unroll
    for (int i = 0; i < TM; i++) {
        int m = m0 + r * TM + i;
        if (m >= M) continue;
#pragma unroll
        for (int j = 0; j < TN; j += 4) {
            int n = n0 + c * TN + j;
            if (n < N) {
                float4 v;
                v.x = acc[i][j + 0] + (direct ? bias[n + 0] : 0.f);
                v.y = acc[i][j + 1] + (direct ? bias[n + 1] : 0.f);
                v.z = acc[i][j + 2] + (direct ? bias[n + 2] : 0.f);
                v.w = acc[i][j + 3] + (direct ? bias[n + 3] : 0.f);
                *(float4*)(dst + (size_t)m * N + n) = v;
            }
        }
    }
}

// ---------------- merged GRU matmuls: slabs 0..7 = xm (x1 built inline), 8..15 = hm
__global__ void gru_mm_kernel(const int* __restrict__ x,
                              const float* __restrict__ query,
                              const float* __restrict__ emb,
                              const float* __restrict__ dec_hidden,
                              const float* __restrict__ Wk,
                              const float* __restrict__ Wr,
                              float* __restrict__ part) {
    const int NN = 3 * UNITS;
    __shared__ float As[32][65];
    __shared__ float Ws[32][64];
    const int tid = threadIdx.x;
    const int r = tid >> 4;
    const int c = tid & 15;
    const int n0 = blockIdx.x * 64;
    const bool isX = blockIdx.z < 8;
    const int kbase = (isX ? blockIdx.z : blockIdx.z - 8) * 64;
    const float* W = isX ? Wk : Wr;

    float acc[4][4];
#pragma unroll
    for (int i = 0; i < 4; i++)
#pragma unroll
        for (int j = 0; j < 4; j++) acc[i][j] = 0.f;

    for (int kk = kbase; kk < kbase + 64; kk += 32) {
#pragma unroll
        for (int pass = 0; pass < 2; pass++) {
            int idx = pass * 1024 + tid * 4;
            int m = idx >> 5;
            int k = idx & 31;
            int gk = kk + k;
            float4 v;
            if (isX) {
                if (gk < EMB)
                    v = *(const float4*)(emb + (size_t)x[m] * EMB + gk);
                else
                    v = *(const float4*)(query + (size_t)m * QDIM + gk - EMB);
            } else {
                v = *(const float4*)(dec_hidden + (size_t)m * UNITS + gk);
            }
            As[k + 0][m] = v.x;
            As[k + 1][m] = v.y;
            As[k + 2][m] = v.z;
            As[k + 3][m] = v.w;
        }
#pragma unroll
        for (int pass = 0; pass < 2; pass++) {
            int idx = pass * 1024 + tid * 4;
            int k = idx >> 6;
            int n = idx & 63;
            *(float4*)&Ws[k][n] = *(const float4*)(W + (size_t)(kk + k) * NN + n0 + n);
        }
        __syncthreads();
#pragma unroll
        for (int k = 0; k < 32; k++) {
            float a0 = As[k][r * 4 + 0];
            float a1 = As[k][r * 4 + 1];
            float a2 = As[k][r * 4 + 2];
            float a3 = As[k][r * 4 + 3];
            float4 b = *(const float4*)&Ws[k][c * 4];
            acc[0][0] = fmaf(a0, b.x, acc[0][0]); acc[0][1] = fmaf(a0, b.y, acc[0][1]);
            acc[0][2] = fmaf(a0, b.z, acc[0][2]); acc[0][3] = fmaf(a0, b.w, acc[0][3]);
            acc[1][0] = fmaf(a1, b.x, acc[1][0]); acc[1][1] = fmaf(a1, b.y, acc[1][1]);
            acc[1][2] = fmaf(a1, b.z, acc[1][2]); acc[1][3] = fmaf(a1, b.w, acc[1][3]);
            acc[2][0] = fmaf(a2, b.x, acc[2][0]); acc[2][1] = fmaf(a2, b.y, acc[2][1]);
            acc[2][2] = fmaf(a2, b.z, acc[2][2]); acc[2][3] = fmaf(a2, b.w, acc[2][3]);
            acc[3][0] = fmaf(a3, b.x, acc[3][0]); acc[3][1] = fmaf(a3, b.y, acc[3][1]);
            acc[3][2] = fmaf(a3, b.z, acc[3][2]); acc[3][3] = fmaf(a3, b.w, acc[3][3]);
        }
        __syncthreads();
    }

    float* dst = part + (size_t)blockIdx.z * BATCH * NN;
#pragma unroll
    for (int i = 0; i < 4; i++) {
        int m = r * 4 + i;
        int n = n0 + c * 4;
        float4 v = make_float4(acc[i][0], acc[i][1], acc[i][2], acc[i][3]);
        *(float4*)(dst + (size_t)m * NN + n) = v;
    }
}

// ---------------- reduce K-split partials + bias ----------------
__global__ void reduce_bias_kernel(const float* __restrict__ part,
                                   const float* __restrict__ bias,
                                   float* __restrict__ C,
                                   int MN, int N, int S) {
    int i = blockIdx.x * 256 + threadIdx.x;
    if (i >= MN) return;
    float s = 0.f;
    for (int z = 0; z < S; z++) s += part[(size_t)z * MN + i];
    C[i] = s + bias[i % N];
}

// ---------------- GRU gates: sums 8 xm slabs + 8 hm slabs + bias ----------------
__global__ void gru_gates_kernel(const float* __restrict__ part,
                                 const float* __restrict__ bias,
                                 const float* __restrict__ h_in,
                                 float* __restrict__ h_scratch,
                                 float* __restrict__ out_state,
                                 float* __restrict__ out_output) {
    const int NN = 3 * UNITS;
    int b = blockIdx.x;
    int u = threadIdx.x;               // 512
    float xz = bias[u], xr = bias[UNITS + u], xh = bias[2 * UNITS + u];
    float hz = bias[NN + u], hr = bias[NN + UNITS + u], hh = bias[NN + 2 * UNITS + u];
#pragma unroll
    for (int z = 0; z < 8; z++) {
        const float* px = part + (size_t)z * BATCH * NN + b * NN;
        const float* ph = part + (size_t)(8 + z) * BATCH * NN + b * NN;
        xz += px[u]; xr += px[UNITS + u]; xh += px[2 * UNITS + u];
        hz += ph[u]; hr += ph[UNITS + u]; hh += ph[2 * UNITS + u];
    }
    float z = 1.f / (1.f + expf(-(xz + hz)));
    float r = 1.f / (1.f + expf(-(xr + hr)));
    float hc = tanhf(xh + r * hh);
    float h = h_in[b * UNITS + u];
    float hn = z * h + (1.f - z) * hc;
    h_scratch[b * UNITS + u] = hn;
    if (out_state)  out_state[b * UNITS + u] = hn;
    if (out_output) out_output[b * UNITS + u] = hn;
}

// ---------------- attention: R12-proven fp32 body, writes exp(score) ------------
// grid (ceil(POI/128), BATCH/4), block 128. tanh in [-1,1] bounds |score| ~ 20,
// so unshifted exp is safe in fp32 (proven R13/R14: rel_err unchanged).
__global__ void attn_score_kernel(const float* __restrict__ vproj,
                                  const float* __restrict__ qproj,
                                  const float* __restrict__ Vw,
                                  const float* __restrict__ Vb,
                                  float* __restrict__ score_exp) {
    __shared__ float q_s[4][UNITS];
    __shared__ float vw_s[UNITS];
    __shared__ float v_s[128][33];
    const int tid = threadIdx.x;       // 128
    const int p0 = blockIdx.x * 128;
    const int b0 = blockIdx.y * 4;

    for (int t = tid; t < 4 * UNITS; t += 128) {
        int b = t >> 9, u = t & 511;
        q_s[b][u] = qproj[(b0 + b) * UNITS + u];
    }
    for (int t = tid; t < UNITS; t += 128) vw_s[t] = Vw[t];

    float acc0 = 0.f, acc1 = 0.f, acc2 = 0.f, acc3 = 0.f;
    for (int u0 = 0; u0 < UNITS; u0 += 32) {
        __syncthreads();
        for (int t = tid; t < 128 * 32; t += 128) {
            int p = t >> 5, j = t & 31;
            v_s[p][j] = (p0 + p < POI) ? vproj[(size_t)(p0 + p) * UNITS + u0 + j] : 0.f;
        }
        __syncthreads();
#pragma unroll
        for (int j = 0; j < 32; ++j) {
            float v  = v_s[tid][j];
            float vw = vw_s[u0 + j];
            acc0 = fmaf(vw, tanh_ap(v + q_s[0][u0 + j]), acc0);
            acc1 = fmaf(vw, tanh_ap(v + q_s[1][u0 + j]), acc1);
            acc2 = fmaf(vw, tanh_ap(v + q_s[2][u0 + j]), acc2);
            acc3 = fmaf(vw, tanh_ap(v + q_s[3][u0 + j]), acc3);
        }
    }
    if (p0 + tid < POI) {
        float vb = Vb[0];
        score_exp[(size_t)(b0 + 0) * POI + p0 + tid] = __expf(acc0 + vb);
        score_exp[(size_t)(b0 + 1) * POI + p0 + tid] = __expf(acc1 + vb);
        score_exp[(size_t)(b0 + 2) * POI + p0 + tid] = __expf(acc2 + vb);
        score_exp[(size_t)(b0 + 3) * POI + p0 + tid] = __expf(acc3 + vb);
    }
}

// ---------------- context partials over exp weights + per-chunk exp-sums --------
__global__ void context_partial_kernel(const float* __restrict__ eattn,
                                       const float* __restrict__ emb,
                                       float* __restrict__ part,
                                       float* __restrict__ sums) {
    const int PC = POI / NCH;          // 500
    int b0 = blockIdx.x * 4;
    int ch = blockIdx.y;
    int e  = threadIdx.x;              // 256 == EMB
    int p0 = ch * PC;
    const float* a0 = eattn + (size_t)(b0 + 0) * POI;
    const float* a1 = eattn + (size_t)(b0 + 1) * POI;
    const float* a2 = eattn + (size_t)(b0 + 2) * POI;
    const float* a3 = eattn + (size_t)(b0 + 3) * POI;
    float c0 = 0.f, c1 = 0.f, c2 = 0.f, c3 = 0.f;
    float s0 = 0.f, s1 = 0.f, s2 = 0.f, s3 = 0.f;
#pragma unroll 4
    for (int p = p0; p < p0 + PC; ++p) {
        float w0 = a0[p], w1 = a1[p], w2 = a2[p], w3 = a3[p];
        float ev = emb[p * EMB + e];
        c0 = fmaf(w0, ev, c0); s0 += w0;
        c1 = fmaf(w1, ev, c1); s1 += w1;
        c2 = fmaf(w2, ev, c2); s2 += w2;
        c3 = fmaf(w3, ev, c3); s3 += w3;
    }
    part[(ch * BATCH + b0 + 0) * EMB + e] = c0;
    part[(ch * BATCH + b0 + 1) * EMB + e] = c1;
    part[(ch * BATCH + b0 + 2) * EMB + e] = c2;
    part[(ch * BATCH + b0 + 3) * EMB + e] = c3;
    if (e == 0) {
        sums[ch * BATCH + b0 + 0] = s0;
        sums[ch * BATCH + b0 + 1] = s1;
        sums[ch * BATCH + b0 + 2] = s2;
        sums[ch * BATCH + b0 + 3] = s3;
    }
}

// ---------------- ctx = (sum of partials) / (sum of exp) ----------------
__global__ void ctx_reduce_kernel(const float* __restrict__ part,
                                  const float* __restrict__ sums,
                                  float* __restrict__ ctx) {
    int b = blockIdx.x;
    int e = threadIdx.x;               // 256
    float num = 0.f, den = 0.f;
#pragma unroll
    for (int ch = 0; ch < NCH; ch++) {
        num += part[(ch * BATCH + b) * EMB + e];
        den += sums[ch * BATCH + b];
    }
    ctx[b * EMB + e] = num / den;
}

// ---------------- launch ----------------
extern "C" void kernel_launch(void* const* d_in, const int* in_sizes, int n_in,
                              void* d_out, int out_size) {
    const int*   x          = (const int*)  d_in[0];
    const float* query      = (const float*)d_in[1];
    const float* emb        = (const float*)d_in[2];
    // d_in[3] = A_hat (unused)
    const float* dec_hidden = (const float*)d_in[4];
    const float* cat_dec    = (const float*)d_in[5];
    const float* gru_kernel = (const float*)d_in[6];
    const float* gru_rec    = (const float*)d_in[7];
    const float* gru_bias   = (const float*)d_in[8];
    const float* W1_w       = (const float*)d_in[9];
    const float* W1_b       = (const float*)d_in[10];
    const float* W2_w       = (const float*)d_in[11];
    const float* W2_b       = (const float*)d_in[12];
    const float* V_w        = (const float*)d_in[13];
    const float* V_b        = (const float*)d_in[14];
    const float* fc_w       = (const float*)d_in[15];
    const float* fc_b       = (const float*)d_in[16];

    float* out        = (float*)d_out;
    float* out_logits = out;
    float* out_state  = (out_size >= BATCH * POI + BATCH * UNITS)
                        ? out + BATCH * POI : nullptr;
    float* out_output = (out_size >= BATCH * POI + 2 * BATCH * UNITS)
                        ? out + BATCH * POI + BATCH * UNITS : nullptr;

    float *g_h_p, *g_qp_p, *g_ctx_p, *g_vp_p, *g_sc_p, *g_cp_p, *g_cs_p;
    float *g_grup_p, *g_qpp_p, *g_fcp_p;
    __nv_bfloat16 *g_embbf_p, *g_w1tbf_p;
    cudaGetSymbolAddress((void**)&g_h_p,     g_h);
    cudaGetSymbolAddress((void**)&g_qp_p,    g_qproj);
    cudaGetSymbolAddress((void**)&g_ctx_p,   g_ctx);
    cudaGetSymbolAddress((void**)&g_vp_p,    g_vproj);
    cudaGetSymbolAddress((void**)&g_sc_p,    g_score);
    cudaGetSymbolAddress((void**)&g_cp_p,    g_ctxpart);
    cudaGetSymbolAddress((void**)&g_cs_p,    g_ctxsums);
    cudaGetSymbolAddress((void**)&g_grup_p,  g_gru_part);
    cudaGetSymbolAddress((void**)&g_qpp_p,   g_qp_part);
    cudaGetSymbolAddress((void**)&g_fcp_p,   g_fc_part);
    cudaGetSymbolAddress((void**)&g_embbf_p, g_emb_bf);
    cudaGetSymbolAddress((void**)&g_w1tbf_p, g_w1t_bf);

    // One-time stream/event setup (on the uncaptured correctness call).
    static cudaStream_t s2 = nullptr, s3 = nullptr;
    static cudaEvent_t evFork = nullptr, evVP = nullptr, evH = nullptr, evFC = nullptr;
    if (!s2) {
        cudaStreamCreateWithFlags(&s2, cudaStreamNonBlocking);
        cudaStreamCreateWithFlags(&s3, cudaStreamNonBlocking);
        cudaEventCreateWithFlags(&evFork, cudaEventDisableTiming);
        cudaEventCreateWithFlags(&evVP, cudaEventDisableTiming);
        cudaEventCreateWithFlags(&evH, cudaEventDisableTiming);
        cudaEventCreateWithFlags(&evFC, cudaEventDisableTiming);
    }

    // ---- fork ----
    cudaEventRecord(evFork, 0);
    cudaStreamWaitEvent(s2, evFork, 0);
    cudaStreamWaitEvent(s3, evFork, 0);

    // s2: bf16 convert, then vproj via HMMA tensor cores (320 CTAs)
    convert_bf16_kernel<<<(POI * EMB + 255) / 256, 256, 0, s2>>>(
        emb, W1_w, g_embbf_p, g_w1tbf_p);
    vproj_hmma_kernel<<<dim3(UNITS / 64, (POI + 127) / 128), 256, 0, s2>>>(
        g_embbf_p, g_w1tbf_p, W1_b, g_vp_p);
    cudaEventRecord(evVP, s2);

    // s3: fc cat_dec term (K rows 768..1279), slabs 0..3 — needs only inputs
    gemm_v2_kernel<64, 128, 4, 8><<<dim3((POI + 127) / 128, 1, 4), 256, 0, s3>>>(
        cat_dec, fc_w + (size_t)(EMB + UNITS) * POI, nullptr, g_fcp_p,
        BATCH, POI, UNITS, 128);

    // main: GRU chain
    gru_mm_kernel<<<dim3(3 * UNITS / 64, 1, 16), 256>>>(
        x, query, emb, dec_hidden, gru_kernel, gru_rec, g_grup_p);
    gru_gates_kernel<<<BATCH, UNITS>>>(g_grup_p, gru_bias, dec_hidden,
                                       g_h_p, out_state, out_output);
    cudaEventRecord(evH, 0);

    // s3: fc output_ term (K rows 256..767), slabs 4..7 — needs h
    cudaStreamWaitEvent(s3, evH, 0);
    gemm_v2_kernel<64, 128, 4, 8><<<dim3((POI + 127) / 128, 1, 4), 256, 0, s3>>>(
        g_h_p, fc_w + (size_t)EMB * POI, nullptr, g_fcp_p + (size_t)4 * BATCH * POI,
        BATCH, POI, UNITS, 128);
    cudaEventRecord(evFC, s3);

    // main: q_proj = h @ W2 + b (split 8, then small reduce)
    gemm_v2_kernel<64, 64, 4, 4><<<dim3(UNITS / 64, 1, 8), 256>>>(
        g_h_p, W2_w, nullptr, g_qpp_p, BATCH, UNITS, UNITS, 64);
    reduce_bias_kernel<<<(BATCH * UNITS + 255) / 256, 256>>>(
        g_qpp_p, W2_b, g_qp_p, BATCH * UNITS, UNITS, 8);

    // main: attention (waits on vproj); writes exp(score) directly
    cudaStreamWaitEvent(0, evVP, 0);
    attn_score_kernel<<<dim3((POI + 127) / 128, BATCH / 4), 128>>>(
        g_vp_p, g_qp_p, V_w, V_b, g_sc_p);

    // main: context partials (exp-weighted) + per-chunk exp sums, then normalize
    context_partial_kernel<<<dim3(BATCH / 4, NCH), 256>>>(g_sc_p, emb, g_cp_p, g_cs_p);
    ctx_reduce_kernel<<<BATCH, 256>>>(g_cp_p, g_cs_p, g_ctx_p);

    // main: fc context term (K rows 0..255), slabs 8..9
    gemm_v2_kernel<64, 128, 4, 8><<<dim3((POI + 127) / 128, 1, 2), 256>>>(
        g_ctx_p, fc_w, nullptr, g_fcp_p + (size_t)8 * BATCH * POI,
        BATCH, POI, EMB, 128);

    // main: final reduce over 10 slabs + bias (waits on s3's fc terms)
    cudaStreamWaitEvent(0, evFC, 0);
    reduce_bias_kernel<<<(BATCH * POI + 255) / 256, 256>>>(
        g_fcp_p, fc_b, out_logits, BATCH * POI, POI, 10);
}

// round 16
// speedup vs baseline: 1.3792x; 1.2417x over previous
#include <cuda_runtime.h>
#include <cuda_bf16.h>
#include <math.h>
#include <cstdint>

#define POI   5000
#define EMB   256
#define UNITS 512
#define QDIM  256
#define BATCH 64
#define X1DIM  (EMB + QDIM)        // 512
#define NPB    40                  // attn p-blocks (ceil(5000/128))

// ---------------- scratch (no cudaMalloc allowed; disjoint per concurrent use) --
__device__ float g_h[BATCH * UNITS];
__device__ float g_qproj[BATCH * UNITS];
__device__ float g_ctx[BATCH * EMB];
__device__ float g_vproj[POI * UNITS];                 // 10.24 MB
__device__ float g_ctxpart[NPB * BATCH * EMB];         // 2.6 MB
__device__ float g_ctxsums[NPB * BATCH];
__device__ float g_gru_part[16 * BATCH * 3 * UNITS];   // 6.3 MB
__device__ float g_qp_part[8 * BATCH * UNITS];         // 1.0 MB
__device__ float g_fc_part[10 * BATCH * POI];          // 12.8 MB
__device__ __nv_bfloat16 g_emb_bf[POI * EMB];          // 2.56 MB
__device__ __nv_bfloat16 g_w1t_bf[UNITS * EMB];        // 0.26 MB (W1 transposed)

__device__ __forceinline__ float tanh_ap(float x) {
    float y;
    asm("tanh.approx.f32 %0, %1;" : "=f"(y) : "f"(x));
    return y;
}

// ---------------- fp32 -> bf16 conversion (emb row-major, W1 transposed) --------
__global__ void convert_bf16_kernel(const float* __restrict__ emb,
                                    const float* __restrict__ W1,
                                    __nv_bfloat16* __restrict__ emb_bf,
                                    __nv_bfloat16* __restrict__ w1t_bf) {
    int idx = blockIdx.x * 256 + threadIdx.x;
    if (idx < POI * EMB) emb_bf[idx] = __float2bfloat16(emb[idx]);
    if (idx < UNITS * EMB) {
        int u = idx >> 8;          // /EMB
        int k = idx & 255;
        w1t_bf[idx] = __float2bfloat16(W1[k * UNITS + u]);
    }
}

// ---------------- vproj via HMMA (mma.sync m16n8k16 bf16) — R12-proven ----------
__global__ void __launch_bounds__(256)
vproj_hmma_kernel(const __nv_bfloat16* __restrict__ emb_bf,
                  const __nv_bfloat16* __restrict__ w1t_bf,
                  const float* __restrict__ W1_b,
                  float* __restrict__ vproj) {
    const int warp = threadIdx.x >> 5;
    const int lane = threadIdx.x & 31;
    const int grp = lane >> 2;
    const int qid = lane & 3;
    const int n0 = blockIdx.x * 64;
    const int m0 = blockIdx.y * 128 + warp * 16;

    const int row0 = m0 + grp;
    const int row1 = m0 + grp + 8;
    const bool v0 = row0 < POI;
    const bool v1 = row1 < POI;

    float d[8][4];
#pragma unroll
    for (int nt = 0; nt < 8; nt++)
#pragma unroll
        for (int j = 0; j < 4; j++) d[nt][j] = 0.f;

#pragma unroll 4
    for (int k0 = 0; k0 < EMB; k0 += 16) {
        uint32_t a0 = 0, a1 = 0, a2 = 0, a3 = 0;
        if (v0) {
            const uint32_t* pa = (const uint32_t*)(emb_bf + (size_t)row0 * EMB + k0 + qid * 2);
            a0 = pa[0];
            a2 = pa[4];
        }
        if (v1) {
            const uint32_t* pa = (const uint32_t*)(emb_bf + (size_t)row1 * EMB + k0 + qid * 2);
            a1 = pa[0];
            a3 = pa[4];
        }
#pragma unroll
        for (int nt = 0; nt < 8; nt++) {
            const uint32_t* pb = (const uint32_t*)(w1t_bf + (size_t)(n0 + nt * 8 + grp) * EMB + k0 + qid * 2);
            uint32_t b0 = pb[0];
            uint32_t b1 = pb[4];
            asm volatile(
                "mma.sync.aligned.m16n8k16.row.col.f32.bf16.bf16.f32 "
                "{%0,%1,%2,%3}, {%4,%5,%6,%7}, {%8,%9}, {%0,%1,%2,%3};"
                : "+f"(d[nt][0]), "+f"(d[nt][1]), "+f"(d[nt][2]), "+f"(d[nt][3])
                : "r"(a0), "r"(a1), "r"(a2), "r"(a3), "r"(b0), "r"(b1));
        }
    }

    if (v0) {
        float* dst = vproj + (size_t)row0 * UNITS;
#pragma unroll
        for (int nt = 0; nt < 8; nt++) {
            int n = n0 + nt * 8 + qid * 2;
            float2 v = make_float2(d[nt][0] + W1_b[n], d[nt][1] + W1_b[n + 1]);
            *(float2*)(dst + n) = v;
        }
    }
    if (v1) {
        float* dst = vproj + (size_t)row1 * UNITS;
#pragma unroll
        for (int nt = 0; nt < 8; nt++) {
            int n = n0 + nt * 8 + qid * 2;
            float2 v = make_float2(d[nt][2] + W1_b[n], d[nt][3] + W1_b[n + 1]);
            *(float2*)(dst + n) = v;
        }
    }
}

// ---------------- gemm_v2: C[M,N] = A[M,K] @ W[K,N] (+bias iff gridDim.z==1) -----
template <int BM, int BN, int TM, int TN>
__global__ void gemm_v2_kernel(const float* __restrict__ A,
                               const float* __restrict__ W,
                               const float* __restrict__ bias,
                               float* __restrict__ out,
                               int M, int N, int K, int kchunk) {
    __shared__ float As[32][BM + 1];
    __shared__ float Ws[32][BN];
    const int tid = threadIdx.x;
    const int r = tid >> 4;
    const int c = tid & 15;
    const int n0 = blockIdx.x * BN;
    const int m0 = blockIdx.y * BM;
    const int kbase = blockIdx.z * kchunk;

    float acc[TM][TN];
#pragma unroll
    for (int i = 0; i < TM; i++)
#pragma unroll
        for (int j = 0; j < TN; j++) acc[i][j] = 0.f;

    for (int kk = kbase; kk < kbase + kchunk; kk += 32) {
#pragma unroll
        for (int pass = 0; pass < (BM * 32) / 1024; pass++) {
            int idx = pass * 1024 + tid * 4;
            int m = idx >> 5;
            int k = idx & 31;
            float4 v = make_float4(0.f, 0.f, 0.f, 0.f);
            if (m0 + m < M) v = *(const float4*)(A + (size_t)(m0 + m) * K + kk + k);
            As[k + 0][m] = v.x;
            As[k + 1][m] = v.y;
            As[k + 2][m] = v.z;
            As[k + 3][m] = v.w;
        }
#pragma unroll
        for (int pass = 0; pass < (32 * BN) / 1024; pass++) {
            int idx = pass * 1024 + tid * 4;
            int k = idx / BN;
            int n = idx % BN;
            float4 v = make_float4(0.f, 0.f, 0.f, 0.f);
            if (n0 + n < N) v = *(const float4*)(W + (size_t)(kk + k) * N + n0 + n);
            *(float4*)&Ws[k][n] = v;
        }
        __syncthreads();
#pragma unroll
        for (int k = 0; k < 32; k++) {
            float a[TM];
#pragma unroll
            for (int i = 0; i < TM; i++) a[i] = As[k][r * TM + i];
            float b[TN];
#pragma unroll
            for (int j = 0; j < TN; j += 4)
                *(float4*)&b[j] = *(const float4*)&Ws[k][c * TN + j];
#pragma unroll
            for (int i = 0; i < TM; i++)
#pragma unroll
                for (int j = 0; j < TN; j++)
                    acc[i][j] = fmaf(a[i], b[j], acc[i][j]);
        }
        __syncthreads();
    }

    const bool direct = (gridDim.z == 1);
    float* dst = direct ? out : out + (size_t)blockIdx.z * M * N;
#pragma unroll
    for (int i = 0; i < TM; i++) {
        int m = m0 + r * TM + i;
        if (m >= M) continue;
#pragma unroll
        for (int j = 0; j < TN; j += 4) {
            int n = n0 + c * TN + j;
            if (n < N) {
                float4 v;
                v.x = acc[i][j + 0] + (direct ? bias[n + 0] : 0.f);
                v.y = acc[i][j + 1] + (direct ? bias[n + 1] : 0.f);
                v.z = acc[i][j + 2] + (direct ? bias[n + 2] : 0.f);
                v.w = acc[i][j + 3] + (direct ? bias[n + 3] : 0.f);
                *(float4*)(dst + (size_t)m * N + n) = v;
            }
        }
    }
}

// ---------------- merged GRU matmuls: slabs 0..7 = xm (x1 built inline), 8..15 = hm
__global__ void gru_mm_kernel(const int* __restrict__ x,
                              const float* __restrict__ query,
                              const float* __restrict__ emb,
                              const float* __restrict__ dec_hidden,
                              const float* __restrict__ Wk,
                              const float* __restrict__ Wr,
                              float* __restrict__ part) {
    const int NN = 3 * UNITS;
    __shared__ float As[32][65];
    __shared__ float Ws[32][64];
    const int tid = threadIdx.x;
    const int r = tid >> 4;
    const int c = tid & 15;
    const int n0 = blockIdx.x * 64;
    const bool isX = blockIdx.z < 8;
    const int kbase = (isX ? blockIdx.z : blockIdx.z - 8) * 64;
    const float* W = isX ? Wk : Wr;

    float acc[4][4];
#pragma unroll
    for (int i = 0; i < 4; i++)
#pragma unroll
        for (int j = 0; j < 4; j++) acc[i][j] = 0.f;

    for (int kk = kbase; kk < kbase + 64; kk += 32) {
#pragma unroll
        for (int pass = 0; pass < 2; pass++) {
            int idx = pass * 1024 + tid * 4;
            int m = idx >> 5;
            int k = idx & 31;
            int gk = kk + k;
            float4 v;
            if (isX) {
                if (gk < EMB)
                    v = *(const float4*)(emb + (size_t)x[m] * EMB + gk);
                else
                    v = *(const float4*)(query + (size_t)m * QDIM + gk - EMB);
            } else {
                v = *(const float4*)(dec_hidden + (size_t)m * UNITS + gk);
            }
            As[k + 0][m] = v.x;
            As[k + 1][m] = v.y;
            As[k + 2][m] = v.z;
            As[k + 3][m] = v.w;
        }
#pragma unroll
        for (int pass = 0; pass < 2; pass++) {
            int idx = pass * 1024 + tid * 4;
            int k = idx >> 6;
            int n = idx & 63;
            *(float4*)&Ws[k][n] = *(const float4*)(W + (size_t)(kk + k) * NN + n0 + n);
        }
        __syncthreads();
#pragma unroll
        for (int k = 0; k < 32; k++) {
            float a0 = As[k][r * 4 + 0];
            float a1 = As[k][r * 4 + 1];
            float a2 = As[k][r * 4 + 2];
            float a3 = As[k][r * 4 + 3];
            float4 b = *(const float4*)&Ws[k][c * 4];
            acc[0][0] = fmaf(a0, b.x, acc[0][0]); acc[0][1] = fmaf(a0, b.y, acc[0][1]);
            acc[0][2] = fmaf(a0, b.z, acc[0][2]); acc[0][3] = fmaf(a0, b.w, acc[0][3]);
            acc[1][0] = fmaf(a1, b.x, acc[1][0]); acc[1][1] = fmaf(a1, b.y, acc[1][1]);
            acc[1][2] = fmaf(a1, b.z, acc[1][2]); acc[1][3] = fmaf(a1, b.w, acc[1][3]);
            acc[2][0] = fmaf(a2, b.x, acc[2][0]); acc[2][1] = fmaf(a2, b.y, acc[2][1]);
            acc[2][2] = fmaf(a2, b.z, acc[2][2]); acc[2][3] = fmaf(a2, b.w, acc[2][3]);
            acc[3][0] = fmaf(a3, b.x, acc[3][0]); acc[3][1] = fmaf(a3, b.y, acc[3][1]);
            acc[3][2] = fmaf(a3, b.z, acc[3][2]); acc[3][3] = fmaf(a3, b.w, acc[3][3]);
        }
        __syncthreads();
    }

    float* dst = part + (size_t)blockIdx.z * BATCH * NN;
#pragma unroll
    for (int i = 0; i < 4; i++) {
        int m = r * 4 + i;
        int n = n0 + c * 4;
        float4 v = make_float4(acc[i][0], acc[i][1], acc[i][2], acc[i][3]);
        *(float4*)(dst + (size_t)m * NN + n) = v;
    }
}

// ---------------- reduce K-split partials + bias ----------------
__global__ void reduce_bias_kernel(const float* __restrict__ part,
                                   const float* __restrict__ bias,
                                   float* __restrict__ C,
                                   int MN, int N, int S) {
    int i = blockIdx.x * 256 + threadIdx.x;
    if (i >= MN) return;
    float s = 0.f;
    for (int z = 0; z < S; z++) s += part[(size_t)z * MN + i];
    C[i] = s + bias[i % N];
}

// ---------------- GRU gates: sums 8 xm slabs + 8 hm slabs + bias ----------------
__global__ void gru_gates_kernel(const float* __restrict__ part,
                                 const float* __restrict__ bias,
                                 const float* __restrict__ h_in,
                                 float* __restrict__ h_scratch,
                                 float* __restrict__ out_state,
                                 float* __restrict__ out_output) {
    const int NN = 3 * UNITS;
    int b = blockIdx.x;
    int u = threadIdx.x;               // 512
    float xz = bias[u], xr = bias[UNITS + u], xh = bias[2 * UNITS + u];
    float hz = bias[NN + u], hr = bias[NN + UNITS + u], hh = bias[NN + 2 * UNITS + u];
#pragma unroll
    for (int z = 0; z < 8; z++) {
        const float* px = part + (size_t)z * BATCH * NN + b * NN;
        const float* ph = part + (size_t)(8 + z) * BATCH * NN + b * NN;
        xz += px[u]; xr += px[UNITS + u]; xh += px[2 * UNITS + u];
        hz += ph[u]; hr += ph[UNITS + u]; hh += ph[2 * UNITS + u];
    }
    float z = 1.f / (1.f + expf(-(xz + hz)));
    float r = 1.f / (1.f + expf(-(xr + hr)));
    float hc = tanhf(xh + r * hh);
    float h = h_in[b * UNITS + u];
    float hn = z * h + (1.f - z) * hc;
    h_scratch[b * UNITS + u] = hn;
    if (out_state)  out_state[b * UNITS + u] = hn;
    if (out_output) out_output[b * UNITS + u] = hn;
}

// ---------------- fused attention + context partials ----------------
// grid (NPB, BATCH/4), block 128. R12-proven score mainloop; then exp weights
// go to smem and the block computes its own 128p x 256e x 4b context partial
// plus per-block exp sums. No softmax / context kernels needed.
__global__ void attn_ctx_kernel(const float* __restrict__ vproj,
                                const float* __restrict__ qproj,
                                const float* __restrict__ Vw,
                                const float* __restrict__ Vb,
                                const float* __restrict__ emb,
                                float* __restrict__ part,
                                float* __restrict__ sums) {
    __shared__ float q_s[4][UNITS];    // 8 KB
    __shared__ float vw_s[UNITS];      // 2 KB
    __shared__ float v_s[128][33];     // 16.9 KB
    __shared__ float es[4][128];       // 2 KB
    const int tid = threadIdx.x;       // 128
    const int p0 = blockIdx.x * 128;
    const int b0 = blockIdx.y * 4;

    for (int t = tid; t < 4 * UNITS; t += 128) {
        int b = t >> 9, u = t & 511;
        q_s[b][u] = qproj[(b0 + b) * UNITS + u];
    }
    for (int t = tid; t < UNITS; t += 128) vw_s[t] = Vw[t];

    float acc0 = 0.f, acc1 = 0.f, acc2 = 0.f, acc3 = 0.f;
    for (int u0 = 0; u0 < UNITS; u0 += 32) {
        __syncthreads();               // also covers q_s/vw_s on first iter
        for (int t = tid; t < 128 * 32; t += 128) {
            int p = t >> 5, j = t & 31;
            v_s[p][j] = (p0 + p < POI) ? vproj[(size_t)(p0 + p) * UNITS + u0 + j] : 0.f;
        }
        __syncthreads();
#pragma unroll
        for (int j = 0; j < 32; ++j) {
            float v  = v_s[tid][j];
            float vw = vw_s[u0 + j];
            acc0 = fmaf(vw, tanh_ap(v + q_s[0][u0 + j]), acc0);
            acc1 = fmaf(vw, tanh_ap(v + q_s[1][u0 + j]), acc1);
            acc2 = fmaf(vw, tanh_ap(v + q_s[2][u0 + j]), acc2);
            acc3 = fmaf(vw, tanh_ap(v + q_s[3][u0 + j]), acc3);
        }
    }

    // exp weights for this block's 128 p (0 for out-of-range p)
    {
        float vb = Vb[0];
        bool valid = (p0 + tid < POI);
        es[0][tid] = valid ? __expf(acc0 + vb) : 0.f;
        es[1][tid] = valid ? __expf(acc1 + vb) : 0.f;
        es[2][tid] = valid ? __expf(acc2 + vb) : 0.f;
        es[3][tid] = valid ? __expf(acc3 + vb) : 0.f;
    }
    __syncthreads();

    // context partial: thread handles emb cols tid and tid+128
    const int PMAX = (POI - p0 < 128) ? (POI - p0) : 128;
    float n0a = 0.f, n1a = 0.f, n2a = 0.f, n3a = 0.f;   // col tid
    float n0b = 0.f, n1b = 0.f, n2b = 0.f, n3b = 0.f;   // col tid+128
    for (int pp = 0; pp < PMAX; ++pp) {
        const float* erow = emb + (size_t)(p0 + pp) * EMB;
        float ea = erow[tid];
        float eb = erow[tid + 128];
        float w0 = es[0][pp], w1 = es[1][pp], w2 = es[2][pp], w3 = es[3][pp];
        n0a = fmaf(w0, ea, n0a); n0b = fmaf(w0, eb, n0b);
        n1a = fmaf(w1, ea, n1a); n1b = fmaf(w1, eb, n1b);
        n2a = fmaf(w2, ea, n2a); n2b = fmaf(w2, eb, n2b);
        n3a = fmaf(w3, ea, n3a); n3b = fmaf(w3, eb, n3b);
    }
    float* dst = part + ((size_t)blockIdx.x * BATCH + b0) * EMB;
    dst[0 * EMB + tid] = n0a; dst[0 * EMB + tid + 128] = n0b;
    dst[1 * EMB + tid] = n1a; dst[1 * EMB + tid + 128] = n1b;
    dst[2 * EMB + tid] = n2a; dst[2 * EMB + tid + 128] = n2b;
    dst[3 * EMB + tid] = n3a; dst[3 * EMB + tid + 128] = n3b;

    if (tid < 4) {
        float s = 0.f;
        for (int pp = 0; pp < 128; ++pp) s += es[tid][pp];
        sums[blockIdx.x * BATCH + b0 + tid] = s;
    }
}

// ---------------- ctx = (sum of NPB partials) / (sum of exp) ----------------
__global__ void ctx_reduce_kernel(const float* __restrict__ part,
                                  const float* __restrict__ sums,
                                  float* __restrict__ ctx) {
    int b = blockIdx.x;
    int e = threadIdx.x;               // 256
    float num = 0.f, den = 0.f;
    for (int pb = 0; pb < NPB; pb++) {
        num += part[((size_t)pb * BATCH + b) * EMB + e];
        den += sums[pb * BATCH + b];
    }
    ctx[b * EMB + e] = num / den;
}

// ---------------- launch ----------------
extern "C" void kernel_launch(void* const* d_in, const int* in_sizes, int n_in,
                              void* d_out, int out_size) {
    const int*   x          = (const int*)  d_in[0];
    const float* query      = (const float*)d_in[1];
    const float* emb        = (const float*)d_in[2];
    // d_in[3] = A_hat (unused)
    const float* dec_hidden = (const float*)d_in[4];
    const float* cat_dec    = (const float*)d_in[5];
    const float* gru_kernel = (const float*)d_in[6];
    const float* gru_rec    = (const float*)d_in[7];
    const float* gru_bias   = (const float*)d_in[8];
    const float* W1_w       = (const float*)d_in[9];
    const float* W1_b       = (const float*)d_in[10];
    const float* W2_w       = (const float*)d_in[11];
    const float* W2_b       = (const float*)d_in[12];
    const float* V_w        = (const float*)d_in[13];
    const float* V_b        = (const float*)d_in[14];
    const float* fc_w       = (const float*)d_in[15];
    const float* fc_b       = (const float*)d_in[16];

    float* out        = (float*)d_out;
    float* out_logits = out;
    float* out_state  = (out_size >= BATCH * POI + BATCH * UNITS)
                        ? out + BATCH * POI : nullptr;
    float* out_output = (out_size >= BATCH * POI + 2 * BATCH * UNITS)
                        ? out + BATCH * POI + BATCH * UNITS : nullptr;

    float *g_h_p, *g_qp_p, *g_ctx_p, *g_vp_p, *g_cp_p, *g_cs_p;
    float *g_grup_p, *g_qpp_p, *g_fcp_p;
    __nv_bfloat16 *g_embbf_p, *g_w1tbf_p;
    cudaGetSymbolAddress((void**)&g_h_p,     g_h);
    cudaGetSymbolAddress((void**)&g_qp_p,    g_qproj);
    cudaGetSymbolAddress((void**)&g_ctx_p,   g_ctx);
    cudaGetSymbolAddress((void**)&g_vp_p,    g_vproj);
    cudaGetSymbolAddress((void**)&g_cp_p,    g_ctxpart);
    cudaGetSymbolAddress((void**)&g_cs_p,    g_ctxsums);
    cudaGetSymbolAddress((void**)&g_grup_p,  g_gru_part);
    cudaGetSymbolAddress((void**)&g_qpp_p,   g_qp_part);
    cudaGetSymbolAddress((void**)&g_fcp_p,   g_fc_part);
    cudaGetSymbolAddress((void**)&g_embbf_p, g_emb_bf);
    cudaGetSymbolAddress((void**)&g_w1tbf_p, g_w1t_bf);

    // One-time stream/event setup (on the uncaptured correctness call).
    static cudaStream_t s2 = nullptr, s3 = nullptr;
    static cudaEvent_t evFork = nullptr, evVP = nullptr, evH = nullptr, evFC = nullptr;
    if (!s2) {
        cudaStreamCreateWithFlags(&s2, cudaStreamNonBlocking);
        cudaStreamCreateWithFlags(&s3, cudaStreamNonBlocking);
        cudaEventCreateWithFlags(&evFork, cudaEventDisableTiming);
        cudaEventCreateWithFlags(&evVP, cudaEventDisableTiming);
        cudaEventCreateWithFlags(&evH, cudaEventDisableTiming);
        cudaEventCreateWithFlags(&evFC, cudaEventDisableTiming);
    }

    // ---- fork ----
    cudaEventRecord(evFork, 0);
    cudaStreamWaitEvent(s2, evFork, 0);
    cudaStreamWaitEvent(s3, evFork, 0);

    // s2: bf16 convert, then vproj via HMMA tensor cores (320 CTAs)
    convert_bf16_kernel<<<(POI * EMB + 255) / 256, 256, 0, s2>>>(
        emb, W1_w, g_embbf_p, g_w1tbf_p);
    vproj_hmma_kernel<<<dim3(UNITS / 64, (POI + 127) / 128), 256, 0, s2>>>(
        g_embbf_p, g_w1tbf_p, W1_b, g_vp_p);
    cudaEventRecord(evVP, s2);

    // s3: fc cat_dec term (K rows 768..1279), slabs 0..3 — needs only inputs
    gemm_v2_kernel<64, 128, 4, 8><<<dim3((POI + 127) / 128, 1, 4), 256, 0, s3>>>(
        cat_dec, fc_w + (size_t)(EMB + UNITS) * POI, nullptr, g_fcp_p,
        BATCH, POI, UNITS, 128);

    // main: GRU chain
    gru_mm_kernel<<<dim3(3 * UNITS / 64, 1, 16), 256>>>(
        x, query, emb, dec_hidden, gru_kernel, gru_rec, g_grup_p);
    gru_gates_kernel<<<BATCH, UNITS>>>(g_grup_p, gru_bias, dec_hidden,
                                       g_h_p, out_state, out_output);
    cudaEventRecord(evH, 0);

    // s3: fc output_ term (K rows 256..767), slabs 4..7 — needs h
    cudaStreamWaitEvent(s3, evH, 0);
    gemm_v2_kernel<64, 128, 4, 8><<<dim3((POI + 127) / 128, 1, 4), 256, 0, s3>>>(
        g_h_p, fc_w + (size_t)EMB * POI, nullptr, g_fcp_p + (size_t)4 * BATCH * POI,
        BATCH, POI, UNITS, 128);
    cudaEventRecord(evFC, s3);

    // main: q_proj = h @ W2 + b (split 8, then small reduce)
    gemm_v2_kernel<64, 64, 4, 4><<<dim3(UNITS / 64, 1, 8), 256>>>(
        g_h_p, W2_w, nullptr, g_qpp_p, BATCH, UNITS, UNITS, 64);
    reduce_bias_kernel<<<(BATCH * UNITS + 255) / 256, 256>>>(
        g_qpp_p, W2_b, g_qp_p, BATCH * UNITS, UNITS, 8);

    // main: fused attention + context partials (waits on vproj)
    cudaStreamWaitEvent(0, evVP, 0);
    attn_ctx_kernel<<<dim3(NPB, BATCH / 4), 128>>>(
        g_vp_p, g_qp_p, V_w, V_b, emb, g_cp_p, g_cs_p);
    ctx_reduce_kernel<<<BATCH, 256>>>(g_cp_p, g_cs_p, g_ctx_p);

    // main: fc context term (K rows 0..255), slabs 8..9
    gemm_v2_kernel<64, 128, 4, 8><<<dim3((POI + 127) / 128, 1, 2), 256>>>(
        g_ctx_p, fc_w, nullptr, g_fcp_p + (size_t)8 * BATCH * POI,
        BATCH, POI, EMB, 128);

    // main: final reduce over 10 slabs + bias (waits on s3's fc terms)
    cudaStreamWaitEvent(0, evFC, 0);
    reduce_bias_kernel<<<(BATCH * POI + 255) / 256, 256>>>(
        g_fcp_p, fc_b, out_logits, BATCH * POI, POI, 10);
}